// round 15
// baseline (speedup 1.0000x reference)
#include <cuda_runtime.h>
#include <cuda_bf16.h>
#include <stdint.h>
#include <math.h>

#define BDIM 4
#define CDIM 64
#define IDIM 32
#define LDIM 4096
#define LOG2E 1.4426950408889634f

// ---------------- scratch (__device__ globals; allocation-free rule) --------
__device__ __align__(256) __nv_bfloat16 d_qhl[BDIM * LDIM * 64];  // theta*log2e hi|lo
__device__ __align__(256) __nv_bfloat16 d_khl[BDIM * LDIM * 64];
__device__ __align__(256) __nv_bfloat16 d_vhl[BDIM * LDIM * 64];
__device__ __align__(256) float d_ypart[2][BDIM * LDIM * IDIM];
__device__ __align__(256) float d_ls[2][BDIM * LDIM];

// ---------------- helpers ----------------
__device__ __forceinline__ uint32_t smem_u32(const void* p) {
    uint32_t a;
    asm("{ .reg .u64 t; cvta.to.shared.u64 t, %1; cvt.u32.u64 %0, t; }" : "=r"(a) : "l"(p));
    return a;
}
__device__ __forceinline__ void ldsm_x4(uint32_t a, uint32_t* r) {
    asm volatile("ldmatrix.sync.aligned.m8n8.x4.shared.b16 {%0,%1,%2,%3}, [%4];"
                 : "=r"(r[0]), "=r"(r[1]), "=r"(r[2]), "=r"(r[3]) : "r"(a));
}
__device__ __forceinline__ void ldsm_x4t(uint32_t a, uint32_t* r) {
    asm volatile("ldmatrix.sync.aligned.m8n8.x4.trans.shared.b16 {%0,%1,%2,%3}, [%4];"
                 : "=r"(r[0]), "=r"(r[1]), "=r"(r[2]), "=r"(r[3]) : "r"(a));
}
__device__ __forceinline__ void mma_bf16(float* d, const uint32_t* a, const uint32_t* b) {
    asm volatile(
        "mma.sync.aligned.m16n8k16.row.col.f32.bf16.bf16.f32 "
        "{%0,%1,%2,%3}, {%4,%5,%6,%7}, {%8,%9}, {%0,%1,%2,%3};"
        : "+f"(d[0]), "+f"(d[1]), "+f"(d[2]), "+f"(d[3])
        : "r"(a[0]), "r"(a[1]), "r"(a[2]), "r"(a[3]), "r"(b[0]), "r"(b[1]));
}
__device__ __forceinline__ uint32_t cvt_bf16x2(float hi, float lo) {
    uint32_t d;
    asm("cvt.rn.bf16x2.f32 %0, %1, %2;" : "=r"(d) : "f"(hi), "f"(lo));
    return d;
}
__device__ __forceinline__ float ex2f(float a) {
    float d;
    asm("ex2.approx.f32 %0, %1;" : "=f"(d) : "f"(a));
    return d;
}
#define SW(o) ((o) ^ (((o) >> 3) & 0x70))

// ---------------------------------------------------------------------------
// Kernel 1: projections -> bf16 hi/lo split operands, rows [hi32|lo32].
// theta pre-scaled by log2(e). 512 threads, 64-token tile. grid = (64, 4).
// ---------------------------------------------------------------------------
__global__ __launch_bounds__(512) void proj_kernel(
    const float* __restrict__ x,
    const float* __restrict__ g_w, const float* __restrict__ g_b,
    const float* __restrict__ th_w, const float* __restrict__ th_b,
    const float* __restrict__ ph_w, const float* __restrict__ ph_b)
{
    const int b  = blockIdx.y;
    const int l0 = blockIdx.x * 64;
    const int t  = threadIdx.x;

    __shared__ __align__(16) float4 xs4[CDIM][16];
    __shared__ __align__(16) float4 wpack[CDIM][IDIM];
    __shared__ float bs[3][IDIM];

    for (int idx = t; idx < CDIM * 16; idx += 512) {
        int c = idx >> 4, q = idx & 15;
        xs4[c][q] = ((const float4*)(x + ((size_t)b * CDIM + c) * LDIM + l0))[q];
    }
    for (int idx = t; idx < CDIM * IDIM; idx += 512) {
        int o = idx >> 6, c = idx & 63;
        wpack[c][o] = make_float4(g_w[idx], th_w[idx], ph_w[idx], 0.f);
    }
    if (t < IDIM) { bs[0][t] = g_b[t]; bs[1][t] = th_b[t]; bs[2][t] = ph_b[t]; }
    __syncthreads();

    const int o = t & 31;
    const int g = t >> 5;

    float ag[4]  = {0.f, 0.f, 0.f, 0.f};
    float at_[4] = {0.f, 0.f, 0.f, 0.f};
    float ap[4]  = {0.f, 0.f, 0.f, 0.f};

#pragma unroll
    for (int c = 0; c < CDIM; ++c) {
        float4 wv = wpack[c][o];
        float4 xv = xs4[c][g];
        ag[0]  = fmaf(wv.x, xv.x, ag[0]);   ag[1]  = fmaf(wv.x, xv.y, ag[1]);
        ag[2]  = fmaf(wv.x, xv.z, ag[2]);   ag[3]  = fmaf(wv.x, xv.w, ag[3]);
        at_[0] = fmaf(wv.y, xv.x, at_[0]);  at_[1] = fmaf(wv.y, xv.y, at_[1]);
        at_[2] = fmaf(wv.y, xv.z, at_[2]);  at_[3] = fmaf(wv.y, xv.w, at_[3]);
        ap[0]  = fmaf(wv.z, xv.x, ap[0]);   ap[1]  = fmaf(wv.z, xv.y, ap[1]);
        ap[2]  = fmaf(wv.z, xv.z, ap[2]);   ap[3]  = fmaf(wv.z, xv.w, ap[3]);
    }

    const float bg = bs[0][o], bt = bs[1][o], bp = bs[2][o];
#pragma unroll
    for (int j = 0; j < 4; ++j) {
        float gv = ag[j] + bg;
        float tv = (at_[j] + bt) * LOG2E;
        float pv = ap[j] + bp;
        __nv_bfloat16 th = __float2bfloat16(tv);
        __nv_bfloat16 tl = __float2bfloat16(tv - __bfloat162float(th));
        __nv_bfloat16 ph = __float2bfloat16(pv);
        __nv_bfloat16 pl = __float2bfloat16(pv - __bfloat162float(ph));
        __nv_bfloat16 gh = __float2bfloat16(gv);
        __nv_bfloat16 gl = __float2bfloat16(gv - __bfloat162float(gh));
        size_t rbase = ((size_t)b * LDIM + l0 + 4 * g + j) * 64;
        d_qhl[rbase + o]      = th;  d_qhl[rbase + 32 + o] = tl;
        d_khl[rbase + o]      = ph;  d_khl[rbase + 32 + o] = pl;
        d_vhl[rbase + o]      = gh;  d_vhl[rbase + 32 + o] = gl;
    }
}

// ---------------------------------------------------------------------------
// Kernel 2: flash attention, key-split x2, S in 3 ILP banks (chain depth 2),
// Y single bank, (256,2) residency preserved.
// grid = (32 qtiles, 2 key-halves, 4 batch); 256 threads.
// ---------------------------------------------------------------------------
__global__ __launch_bounds__(256, 2) void flash_mma_kernel()
{
    const int q0  = blockIdx.x * 128;
    const int h   = blockIdx.y;
    const int b   = blockIdx.z;
    const int tid = threadIdx.x;
    const int w   = tid >> 5;
    const int l   = tid & 31;

    __shared__ __align__(1024) unsigned char smQ[128 * 128];
    __shared__ __align__(1024) unsigned char smKV[2][16384];

    // ---- stage Q tile ----
    {
        const char* gQ = (const char*)d_qhl + (size_t)(b * LDIM + q0) * 128;
#pragma unroll
        for (int j = 0; j < 4; ++j) {
            uint32_t o = (uint32_t)tid * 64 + j * 16;
            uint4 v = *(const uint4*)(gQ + o);
            *(uint4*)(smQ + SW(o)) = v;
        }
    }
    __syncthreads();

    // ---- Q fragments ----
    uint32_t Qh[2][4], Ql[2][4];
    {
        const uint32_t qb  = smem_u32(smQ);
        const int row = 16 * w + (l & 7) + 8 * ((l >> 3) & 1);
        const int cb  = 16 * ((l >> 4) & 1);
#pragma unroll
        for (int ks = 0; ks < 2; ++ks) {
            uint32_t o = (uint32_t)row * 128 + ks * 32 + cb;
            ldsm_x4(qb + SW(o), Qh[ks]);
            ldsm_x4(qb + SW(o + 64), Ql[ks]);
        }
    }

    float Y[4][4];
#pragma unroll
    for (int n = 0; n < 4; ++n)
#pragma unroll
        for (int i = 0; i < 4; ++i) Y[n][i] = 0.f;
    float ls0 = 0.f, ls1 = 0.f;

    const int half = tid >> 7;
    const uint32_t off0 = (uint32_t)(tid & 127) * 64;
    const char* gsrc = (half ? (const char*)d_vhl : (const char*)d_khl)
                     + ((size_t)b * LDIM + (size_t)h * 2048) * 128;

    uint4 rg[4];
#pragma unroll
    for (int j = 0; j < 4; ++j)
        rg[j] = *(const uint4*)(gsrc + off0 + j * 16);

    for (int t = 0; t < 32; ++t) {
        unsigned char* buf = smKV[t & 1];
#pragma unroll
        for (int j = 0; j < 4; ++j) {
            uint32_t o = (uint32_t)half * 8192 + off0 + j * 16;
            *(uint4*)(buf + SW(o)) = rg[j];
        }
        __syncthreads();
        if (t < 31) {
            const char* p = gsrc + (size_t)(t + 1) * 64 * 128 + off0;
#pragma unroll
            for (int j = 0; j < 4; ++j)
                rg[j] = *(const uint4*)(p + j * 16);
        }

        const uint32_t kb = smem_u32(buf);

        // ---- S via 3 independent banks (2-deep chains), then ex2/split ----
        uint32_t Ph[4][4], Pl[4][4];
#pragma unroll
        for (int n = 0; n < 8; ++n) {
            float SA[4] = {0.f, 0.f, 0.f, 0.f};
            float SB[4] = {0.f, 0.f, 0.f, 0.f};
            float SC[4] = {0.f, 0.f, 0.f, 0.f};
            uint32_t rowb = (uint32_t)(n * 8 + (l & 7)) * 128 + 16 * (l >> 3);
            uint32_t KH[4], KL[4];
            ldsm_x4(kb + SW(rowb),      KH);
            ldsm_x4(kb + SW(rowb + 64), KL);
            mma_bf16(SA, Qh[0], KH + 0);
            mma_bf16(SB, Qh[0], KL + 0);
            mma_bf16(SC, Ql[0], KH + 0);
            mma_bf16(SA, Qh[1], KH + 2);
            mma_bf16(SB, Qh[1], KL + 2);
            mma_bf16(SC, Ql[1], KH + 2);

            float e0 = ex2f((SA[0] + SB[0]) + SC[0]);
            float e1 = ex2f((SA[1] + SB[1]) + SC[1]);
            float e2 = ex2f((SA[2] + SB[2]) + SC[2]);
            float e3 = ex2f((SA[3] + SB[3]) + SC[3]);
            ls0 += e0 + e1;
            ls1 += e2 + e3;
            uint32_t h01 = cvt_bf16x2(e1, e0);
            uint32_t h23 = cvt_bf16x2(e3, e2);
            float h0 = __uint_as_float(h01 << 16);
            float h1 = __uint_as_float(h01 & 0xFFFF0000u);
            float h2 = __uint_as_float(h23 << 16);
            float h3 = __uint_as_float(h23 & 0xFFFF0000u);
            uint32_t l01 = cvt_bf16x2(e1 - h1, e0 - h0);
            uint32_t l23 = cvt_bf16x2(e3 - h3, e2 - h2);
            const int kt = n >> 1, pos = (n & 1) * 2;
            Ph[kt][pos]     = h01;
            Ph[kt][pos + 1] = h23;
            Pl[kt][pos]     = l01;
            Pl[kt][pos + 1] = l23;
        }

        // ---- Y += Ph.Vh + Pl.Vh + Ph.Vl (single bank, as R9) ----
#pragma unroll
        for (int kt = 0; kt < 4; ++kt) {
            uint32_t vrow = (uint32_t)(64 + kt * 16 + (l & 7) + 8 * ((l >> 3) & 1)) * 128
                          + ((l >> 4) & 1) * 16;
#pragma unroll
            for (int np = 0; np < 2; ++np) {
                uint32_t VH[4], VL[4];
                ldsm_x4t(kb + SW(vrow + np * 32),      VH);
                ldsm_x4t(kb + SW(vrow + np * 32 + 64), VL);
                mma_bf16(Y[2 * np],     Ph[kt], VH + 0);
                mma_bf16(Y[2 * np + 1], Ph[kt], VH + 2);
                mma_bf16(Y[2 * np],     Pl[kt], VH + 0);
                mma_bf16(Y[2 * np + 1], Pl[kt], VH + 2);
                mma_bf16(Y[2 * np],     Ph[kt], VL + 0);
                mma_bf16(Y[2 * np + 1], Ph[kt], VL + 2);
            }
        }
    }

    // ---- reduce row sums within quads; store partials ----
    ls0 += __shfl_xor_sync(0xffffffffu, ls0, 1);
    ls0 += __shfl_xor_sync(0xffffffffu, ls0, 2);
    ls1 += __shfl_xor_sync(0xffffffffu, ls1, 1);
    ls1 += __shfl_xor_sync(0xffffffffu, ls1, 2);

    const int r0 = q0 + 16 * w + (l >> 2);
    const int dc = 2 * (l & 3);
    float* yp = d_ypart[h];
#pragma unroll
    for (int n = 0; n < 4; ++n) {
        *(float2*)&yp[((size_t)b * LDIM + r0) * 32 + n * 8 + dc]     = make_float2(Y[n][0], Y[n][1]);
        *(float2*)&yp[((size_t)b * LDIM + r0 + 8) * 32 + n * 8 + dc] = make_float2(Y[n][2], Y[n][3]);
    }
    if ((l & 3) == 0) {
        d_ls[h][(size_t)b * LDIM + r0]     = ls0;
        d_ls[h][(size_t)b * LDIM + r0 + 8] = ls1;
    }
}

// ---------------------------------------------------------------------------
// Kernel 3: merge partials + out = W.y + b + x. (R9 version)
// ---------------------------------------------------------------------------
__global__ __launch_bounds__(256) void out_kernel(
    const float* __restrict__ x,
    const float* __restrict__ W_w, const float* __restrict__ W_b,
    float* __restrict__ out)
{
    const int b  = blockIdx.y;
    const int l0 = blockIdx.x * 64;
    const int t  = threadIdx.x;

    __shared__ __align__(16) float wt[CDIM][IDIM];
    __shared__ float wb_s[CDIM];
    __shared__ float ys[64][33];

    for (int idx = t; idx < CDIM * IDIM; idx += 256)
        ((float*)wt)[idx] = W_w[idx];
    if (t < CDIM) wb_s[t] = W_b[t];

#pragma unroll
    for (int i = 0; i < 2; ++i) {
        int idx = t + i * 256;
        int tok = idx >> 3, fq = idx & 7;
        size_t row = (size_t)b * LDIM + l0 + tok;
        float inv = 1.f / (d_ls[0][row] + d_ls[1][row]);
        float4 a = ((const float4*)(d_ypart[0] + row * 32))[fq];
        float4 c4 = ((const float4*)(d_ypart[1] + row * 32))[fq];
        ys[tok][fq * 4 + 0] = (a.x + c4.x) * inv;
        ys[tok][fq * 4 + 1] = (a.y + c4.y) * inv;
        ys[tok][fq * 4 + 2] = (a.z + c4.z) * inv;
        ys[tok][fq * 4 + 3] = (a.w + c4.w) * inv;
    }
    __syncthreads();

    const int tok = t & 63;
    const int cq  = t >> 6;
    float y[32];
#pragma unroll
    for (int k = 0; k < 32; ++k) y[k] = ys[tok][k];

#pragma unroll
    for (int ci = 0; ci < 16; ++ci) {
        const int c = cq * 16 + ci;
        float a0 = wb_s[c], a1 = 0.f;
        const float4* wr = (const float4*)wt[c];
#pragma unroll
        for (int q = 0; q < 8; ++q) {
            float4 wv = wr[q];
            a0 = fmaf(wv.x, y[4 * q],     a0);
            a1 = fmaf(wv.y, y[4 * q + 1], a1);
            a0 = fmaf(wv.z, y[4 * q + 2], a0);
            a1 = fmaf(wv.w, y[4 * q + 3], a1);
        }
        size_t gi = ((size_t)b * CDIM + c) * LDIM + l0 + tok;
        out[gi] = a0 + a1 + x[gi];
    }
}

// ---------------------------------------------------------------------------
extern "C" void kernel_launch(void* const* d_in, const int* in_sizes, int n_in,
                              void* d_out, int out_size)
{
    const float* x    = (const float*)d_in[0];
    const float* g_w  = (const float*)d_in[1];
    const float* g_b  = (const float*)d_in[2];
    const float* th_w = (const float*)d_in[3];
    const float* th_b = (const float*)d_in[4];
    const float* ph_w = (const float*)d_in[5];
    const float* ph_b = (const float*)d_in[6];
    const float* W_w  = (const float*)d_in[7];
    const float* W_b  = (const float*)d_in[8];
    float* out = (float*)d_out;

    dim3 gp(LDIM / 64, BDIM);
    proj_kernel<<<gp, 512>>>(x, g_w, g_b, th_w, th_b, ph_w, ph_b);

    dim3 gf(LDIM / 128, 2, BDIM);
    flash_mma_kernel<<<gf, 256>>>();

    dim3 go(LDIM / 64, BDIM);
    out_kernel<<<go, 256>>>(x, W_w, W_b, out);
}

// round 16
// speedup vs baseline: 1.1352x; 1.1352x over previous
#include <cuda_runtime.h>
#include <cuda_bf16.h>
#include <stdint.h>
#include <math.h>

#define BDIM 4
#define CDIM 64
#define IDIM 32
#define LDIM 4096
#define NSPLIT 8
#define KEYS_PER_SPLIT (LDIM / NSPLIT)   // 512 keys = 8 tiles of 64
#define LOG2E 1.4426950408889634f

// ---------------- scratch (__device__ globals; allocation-free rule) --------
__device__ __align__(256) __nv_bfloat16 d_qhl[BDIM * LDIM * 64];  // theta*log2e hi|lo
__device__ __align__(256) __nv_bfloat16 d_khl[BDIM * LDIM * 64];
__device__ __align__(256) __nv_bfloat16 d_vhl[BDIM * LDIM * 64];
__device__ __align__(256) float d_ypart[NSPLIT][BDIM * LDIM * IDIM];
__device__ __align__(256) float d_ls[NSPLIT][BDIM * LDIM];

// ---------------- helpers ----------------
__device__ __forceinline__ uint32_t smem_u32(const void* p) {
    uint32_t a;
    asm("{ .reg .u64 t; cvta.to.shared.u64 t, %1; cvt.u32.u64 %0, t; }" : "=r"(a) : "l"(p));
    return a;
}
__device__ __forceinline__ void ldsm_x4(uint32_t a, uint32_t* r) {
    asm volatile("ldmatrix.sync.aligned.m8n8.x4.shared.b16 {%0,%1,%2,%3}, [%4];"
                 : "=r"(r[0]), "=r"(r[1]), "=r"(r[2]), "=r"(r[3]) : "r"(a));
}
__device__ __forceinline__ void ldsm_x4t(uint32_t a, uint32_t* r) {
    asm volatile("ldmatrix.sync.aligned.m8n8.x4.trans.shared.b16 {%0,%1,%2,%3}, [%4];"
                 : "=r"(r[0]), "=r"(r[1]), "=r"(r[2]), "=r"(r[3]) : "r"(a));
}
__device__ __forceinline__ void mma_bf16(float* d, const uint32_t* a, const uint32_t* b) {
    asm volatile(
        "mma.sync.aligned.m16n8k16.row.col.f32.bf16.bf16.f32 "
        "{%0,%1,%2,%3}, {%4,%5,%6,%7}, {%8,%9}, {%0,%1,%2,%3};"
        : "+f"(d[0]), "+f"(d[1]), "+f"(d[2]), "+f"(d[3])
        : "r"(a[0]), "r"(a[1]), "r"(a[2]), "r"(a[3]), "r"(b[0]), "r"(b[1]));
}
__device__ __forceinline__ uint32_t cvt_bf16x2(float hi, float lo) {
    uint32_t d;
    asm("cvt.rn.bf16x2.f32 %0, %1, %2;" : "=r"(d) : "f"(hi), "f"(lo));
    return d;
}
__device__ __forceinline__ float ex2f(float a) {
    float d;
    asm("ex2.approx.f32 %0, %1;" : "=f"(d) : "f"(a));
    return d;
}
#define SW(o) ((o) ^ (((o) >> 3) & 0x70))

// ---------------------------------------------------------------------------
// Kernel 1: projections -> bf16 hi/lo split operands, rows [hi32|lo32].
// theta pre-scaled by log2(e). 512 threads, 64-token tile. grid = (64, 4).
// (R14 version — best measured)
// ---------------------------------------------------------------------------
__global__ __launch_bounds__(512) void proj_kernel(
    const float* __restrict__ x,
    const float* __restrict__ g_w, const float* __restrict__ g_b,
    const float* __restrict__ th_w, const float* __restrict__ th_b,
    const float* __restrict__ ph_w, const float* __restrict__ ph_b)
{
    const int b  = blockIdx.y;
    const int l0 = blockIdx.x * 64;
    const int t  = threadIdx.x;

    __shared__ __align__(16) float4 xs4[CDIM][16];
    __shared__ __align__(16) float4 wpack[CDIM][IDIM];
    __shared__ float bs[3][IDIM];

    for (int idx = t; idx < CDIM * 16; idx += 512) {
        int c = idx >> 4, q = idx & 15;
        xs4[c][q] = ((const float4*)(x + ((size_t)b * CDIM + c) * LDIM + l0))[q];
    }
    for (int idx = t; idx < CDIM * IDIM; idx += 512) {
        int o = idx >> 6, c = idx & 63;
        wpack[c][o] = make_float4(g_w[idx], th_w[idx], ph_w[idx], 0.f);
    }
    if (t < IDIM) { bs[0][t] = g_b[t]; bs[1][t] = th_b[t]; bs[2][t] = ph_b[t]; }
    __syncthreads();

    const int o = t & 31;
    const int g = t >> 5;

    float ag[4]  = {0.f, 0.f, 0.f, 0.f};
    float at_[4] = {0.f, 0.f, 0.f, 0.f};
    float ap[4]  = {0.f, 0.f, 0.f, 0.f};

#pragma unroll
    for (int c = 0; c < CDIM; ++c) {
        float4 wv = wpack[c][o];
        float4 xv = xs4[c][g];
        ag[0]  = fmaf(wv.x, xv.x, ag[0]);   ag[1]  = fmaf(wv.x, xv.y, ag[1]);
        ag[2]  = fmaf(wv.x, xv.z, ag[2]);   ag[3]  = fmaf(wv.x, xv.w, ag[3]);
        at_[0] = fmaf(wv.y, xv.x, at_[0]);  at_[1] = fmaf(wv.y, xv.y, at_[1]);
        at_[2] = fmaf(wv.y, xv.z, at_[2]);  at_[3] = fmaf(wv.y, xv.w, at_[3]);
        ap[0]  = fmaf(wv.z, xv.x, ap[0]);   ap[1]  = fmaf(wv.z, xv.y, ap[1]);
        ap[2]  = fmaf(wv.z, xv.z, ap[2]);   ap[3]  = fmaf(wv.z, xv.w, ap[3]);
    }

    const float bg = bs[0][o], bt = bs[1][o], bp = bs[2][o];
#pragma unroll
    for (int j = 0; j < 4; ++j) {
        float gv = ag[j] + bg;
        float tv = (at_[j] + bt) * LOG2E;
        float pv = ap[j] + bp;
        __nv_bfloat16 th = __float2bfloat16(tv);
        __nv_bfloat16 tl = __float2bfloat16(tv - __bfloat162float(th));
        __nv_bfloat16 ph = __float2bfloat16(pv);
        __nv_bfloat16 pl = __float2bfloat16(pv - __bfloat162float(ph));
        __nv_bfloat16 gh = __float2bfloat16(gv);
        __nv_bfloat16 gl = __float2bfloat16(gv - __bfloat162float(gh));
        size_t rbase = ((size_t)b * LDIM + l0 + 4 * g + j) * 64;
        d_qhl[rbase + o]      = th;  d_qhl[rbase + 32 + o] = tl;
        d_khl[rbase + o]      = ph;  d_khl[rbase + 32 + o] = pl;
        d_vhl[rbase + o]      = gh;  d_vhl[rbase + 32 + o] = gl;
    }
}

// ---------------------------------------------------------------------------
// Kernel 2: flash attention, key-split x8 (wave-balanced), R14 inner loop.
// grid = (32 qtiles, 8 key-chunks, 4 batch) = 1024 CTAs; 256 threads; 2/SM.
// ---------------------------------------------------------------------------
__global__ __launch_bounds__(256, 2) void flash_mma_kernel()
{
    const int q0  = blockIdx.x * 128;
    const int h   = blockIdx.y;          // key chunk (512 keys)
    const int b   = blockIdx.z;
    const int tid = threadIdx.x;
    const int w   = tid >> 5;
    const int l   = tid & 31;

    __shared__ __align__(1024) unsigned char smQ[128 * 128];
    __shared__ __align__(1024) unsigned char smKV[2][16384];

    // ---- stage Q tile ----
    {
        const char* gQ = (const char*)d_qhl + (size_t)(b * LDIM + q0) * 128;
#pragma unroll
        for (int j = 0; j < 4; ++j) {
            uint32_t o = (uint32_t)tid * 64 + j * 16;
            uint4 v = *(const uint4*)(gQ + o);
            *(uint4*)(smQ + SW(o)) = v;
        }
    }
    __syncthreads();

    // ---- Q fragments ----
    uint32_t Qh[2][4], Ql[2][4];
    {
        const uint32_t qb  = smem_u32(smQ);
        const int row = 16 * w + (l & 7) + 8 * ((l >> 3) & 1);
        const int cb  = 16 * ((l >> 4) & 1);
#pragma unroll
        for (int ks = 0; ks < 2; ++ks) {
            uint32_t o = (uint32_t)row * 128 + ks * 32 + cb;
            ldsm_x4(qb + SW(o), Qh[ks]);
            ldsm_x4(qb + SW(o + 64), Ql[ks]);
        }
    }

    float Y[4][4];
#pragma unroll
    for (int n = 0; n < 4; ++n)
#pragma unroll
        for (int i = 0; i < 4; ++i) Y[n][i] = 0.f;
    float ls0 = 0.f, ls1 = 0.f;

    const int half = tid >> 7;
    const uint32_t off0 = (uint32_t)(tid & 127) * 64;
    const char* gsrc = (half ? (const char*)d_vhl : (const char*)d_khl)
                     + ((size_t)b * LDIM + (size_t)h * KEYS_PER_SPLIT) * 128;

    uint4 rg[4];
#pragma unroll
    for (int j = 0; j < 4; ++j)
        rg[j] = *(const uint4*)(gsrc + off0 + j * 16);

    for (int t = 0; t < KEYS_PER_SPLIT / 64; ++t) {
        unsigned char* buf = smKV[t & 1];
#pragma unroll
        for (int j = 0; j < 4; ++j) {
            uint32_t o = (uint32_t)half * 8192 + off0 + j * 16;
            *(uint4*)(buf + SW(o)) = rg[j];
        }
        __syncthreads();
        if (t < KEYS_PER_SPLIT / 64 - 1) {
            const char* p = gsrc + (size_t)(t + 1) * 64 * 128 + off0;
#pragma unroll
            for (int j = 0; j < 4; ++j)
                rg[j] = *(const uint4*)(p + j * 16);
        }

        const uint32_t kb = smem_u32(buf);

        // ---- S then immediate ex2/split (R14 chained accumulators) ----
        uint32_t Ph[4][4], Pl[4][4];
#pragma unroll
        for (int n = 0; n < 8; ++n) {
            float S[4] = {0.f, 0.f, 0.f, 0.f};
            uint32_t rowb = (uint32_t)(n * 8 + (l & 7)) * 128 + 16 * (l >> 3);
            uint32_t KH[4], KL[4];
            ldsm_x4(kb + SW(rowb),      KH);
            ldsm_x4(kb + SW(rowb + 64), KL);
            mma_bf16(S, Qh[0], KH + 0);
            mma_bf16(S, Qh[1], KH + 2);
            mma_bf16(S, Qh[0], KL + 0);
            mma_bf16(S, Qh[1], KL + 2);
            mma_bf16(S, Ql[0], KH + 0);
            mma_bf16(S, Ql[1], KH + 2);

            float e0 = ex2f(S[0]);
            float e1 = ex2f(S[1]);
            float e2 = ex2f(S[2]);
            float e3 = ex2f(S[3]);
            ls0 += e0 + e1;
            ls1 += e2 + e3;
            uint32_t h01 = cvt_bf16x2(e1, e0);
            uint32_t h23 = cvt_bf16x2(e3, e2);
            float h0 = __uint_as_float(h01 << 16);
            float h1 = __uint_as_float(h01 & 0xFFFF0000u);
            float h2 = __uint_as_float(h23 << 16);
            float h3 = __uint_as_float(h23 & 0xFFFF0000u);
            uint32_t l01 = cvt_bf16x2(e1 - h1, e0 - h0);
            uint32_t l23 = cvt_bf16x2(e3 - h3, e2 - h2);
            const int kt = n >> 1, pos = (n & 1) * 2;
            Ph[kt][pos]     = h01;
            Ph[kt][pos + 1] = h23;
            Pl[kt][pos]     = l01;
            Pl[kt][pos + 1] = l23;
        }

        // ---- Y += Ph.Vh + Pl.Vh + Ph.Vl ----
#pragma unroll
        for (int kt = 0; kt < 4; ++kt) {
            uint32_t vrow = (uint32_t)(64 + kt * 16 + (l & 7) + 8 * ((l >> 3) & 1)) * 128
                          + ((l >> 4) & 1) * 16;
#pragma unroll
            for (int np = 0; np < 2; ++np) {
                uint32_t VH[4], VL[4];
                ldsm_x4t(kb + SW(vrow + np * 32),      VH);
                ldsm_x4t(kb + SW(vrow + np * 32 + 64), VL);
                mma_bf16(Y[2 * np],     Ph[kt], VH + 0);
                mma_bf16(Y[2 * np + 1], Ph[kt], VH + 2);
                mma_bf16(Y[2 * np],     Pl[kt], VH + 0);
                mma_bf16(Y[2 * np + 1], Pl[kt], VH + 2);
                mma_bf16(Y[2 * np],     Ph[kt], VL + 0);
                mma_bf16(Y[2 * np + 1], Ph[kt], VL + 2);
            }
        }
    }

    // ---- reduce row sums within quads; store partials ----
    ls0 += __shfl_xor_sync(0xffffffffu, ls0, 1);
    ls0 += __shfl_xor_sync(0xffffffffu, ls0, 2);
    ls1 += __shfl_xor_sync(0xffffffffu, ls1, 1);
    ls1 += __shfl_xor_sync(0xffffffffu, ls1, 2);

    const int r0 = q0 + 16 * w + (l >> 2);
    const int dc = 2 * (l & 3);
    float* yp = d_ypart[h];
#pragma unroll
    for (int n = 0; n < 4; ++n) {
        *(float2*)&yp[((size_t)b * LDIM + r0) * 32 + n * 8 + dc]     = make_float2(Y[n][0], Y[n][1]);
        *(float2*)&yp[((size_t)b * LDIM + r0 + 8) * 32 + n * 8 + dc] = make_float2(Y[n][2], Y[n][3]);
    }
    if ((l & 3) == 0) {
        d_ls[h][(size_t)b * LDIM + r0]     = ls0;
        d_ls[h][(size_t)b * LDIM + r0 + 8] = ls1;
    }
}

// ---------------------------------------------------------------------------
// Kernel 3: merge 8 partials + out = W.y + b + x.
// 64 tokens/block, 256 threads. grid = (64, 4).
// ---------------------------------------------------------------------------
__global__ __launch_bounds__(256) void out_kernel(
    const float* __restrict__ x,
    const float* __restrict__ W_w, const float* __restrict__ W_b,
    float* __restrict__ out)
{
    const int b  = blockIdx.y;
    const int l0 = blockIdx.x * 64;
    const int t  = threadIdx.x;

    __shared__ __align__(16) float wt[CDIM][IDIM];
    __shared__ float wb_s[CDIM];
    __shared__ float ys[64][33];

    for (int idx = t; idx < CDIM * IDIM; idx += 256)
        ((float*)wt)[idx] = W_w[idx];
    if (t < CDIM) wb_s[t] = W_b[t];

#pragma unroll
    for (int i = 0; i < 2; ++i) {
        int idx = t + i * 256;
        int tok = idx >> 3, fq = idx & 7;
        size_t row = (size_t)b * LDIM + l0 + tok;
        float lsum = 0.f;
#pragma unroll
        for (int hh = 0; hh < NSPLIT; ++hh) lsum += d_ls[hh][row];
        float inv = 1.f / lsum;
        float4 acc = make_float4(0.f, 0.f, 0.f, 0.f);
#pragma unroll
        for (int hh = 0; hh < NSPLIT; ++hh) {
            float4 a = ((const float4*)(d_ypart[hh] + row * 32))[fq];
            acc.x += a.x; acc.y += a.y; acc.z += a.z; acc.w += a.w;
        }
        ys[tok][fq * 4 + 0] = acc.x * inv;
        ys[tok][fq * 4 + 1] = acc.y * inv;
        ys[tok][fq * 4 + 2] = acc.z * inv;
        ys[tok][fq * 4 + 3] = acc.w * inv;
    }
    __syncthreads();

    const int tok = t & 63;
    const int cq  = t >> 6;
    float y[32];
#pragma unroll
    for (int k = 0; k < 32; ++k) y[k] = ys[tok][k];

#pragma unroll
    for (int ci = 0; ci < 16; ++ci) {
        const int c = cq * 16 + ci;
        float a0 = wb_s[c], a1 = 0.f;
        const float4* wr = (const float4*)wt[c];
#pragma unroll
        for (int q = 0; q < 8; ++q) {
            float4 wv = wr[q];
            a0 = fmaf(wv.x, y[4 * q],     a0);
            a1 = fmaf(wv.y, y[4 * q + 1], a1);
            a0 = fmaf(wv.z, y[4 * q + 2], a0);
            a1 = fmaf(wv.w, y[4 * q + 3], a1);
        }
        size_t gi = ((size_t)b * CDIM + c) * LDIM + l0 + tok;
        out[gi] = a0 + a1 + x[gi];
    }
}

// ---------------------------------------------------------------------------
extern "C" void kernel_launch(void* const* d_in, const int* in_sizes, int n_in,
                              void* d_out, int out_size)
{
    const float* x    = (const float*)d_in[0];
    const float* g_w  = (const float*)d_in[1];
    const float* g_b  = (const float*)d_in[2];
    const float* th_w = (const float*)d_in[3];
    const float* th_b = (const float*)d_in[4];
    const float* ph_w = (const float*)d_in[5];
    const float* ph_b = (const float*)d_in[6];
    const float* W_w  = (const float*)d_in[7];
    const float* W_b  = (const float*)d_in[8];
    float* out = (float*)d_out;

    dim3 gp(LDIM / 64, BDIM);
    proj_kernel<<<gp, 512>>>(x, g_w, g_b, th_w, th_b, ph_w, ph_b);

    dim3 gf(LDIM / 128, NSPLIT, BDIM);
    flash_mma_kernel<<<gf, 256>>>();

    dim3 go(LDIM / 64, BDIM);
    out_kernel<<<go, 256>>>(x, W_w, W_b, out);
}